// round 4
// baseline (speedup 1.0000x reference)
#include <cuda_runtime.h>
#include <cuda_bf16.h>
#include <math.h>
#include <float.h>

// Problem constants (fixed by the dataset)
#define PB   64
#define PH   32
#define PKVH 8
#define PD   128
#define PBS  128
#define PBLK_PER_SEQ 16
#define PNB  (PB * PBLK_PER_SEQ)   // 1024
#define PG   (PH / PKVH)           // 4
#define PSCALE 0.08838834764831845f

#define KPAD 132                   // padded K row (floats): 4l*4B stride -> conflict-free

// scratch (allocation-free)
__device__ float g_m  [PNB * PKVH * PG];
__device__ float g_l  [PNB * PKVH * PG];
__device__ float g_out[(size_t)PNB * PKVH * PG * PD];

// dynamic smem layout (floats):
//   s_k      : 128*132 = 16896
//   s_q      : 4*128   = 512
//   s_scores : 4*128   = 512
//   s_bias   : 128
//   s_po     : 4*4*128 = 2048
#define SM_FLOATS (128*KPAD + 512 + 512 + 128 + 2048)
#define SM_BYTES  (SM_FLOATS * 4)

__global__ __launch_bounds__(128) void attn_block_kernel(
    const float* __restrict__ query,
    const float* __restrict__ key_cache,
    const float* __restrict__ value_cache,
    const float* __restrict__ k_new,
    const float* __restrict__ v_new,
    const int*   __restrict__ block_list,
    const int*   __restrict__ block_groups,
    const float* __restrict__ block_bias,
    const int*   __restrict__ block_indices,
    const int*   __restrict__ block_offsets)
{
    extern __shared__ float sm[];
    float* s_k      = sm;
    float* s_q      = s_k + 128 * KPAD;
    float* s_scores = s_q + 512;            // [G][128]
    float* s_bias   = s_scores + 512;
    float* s_po     = s_bias + 128;         // [warp][G][128]

    const int n   = blockIdx.x;
    const int kvh = blockIdx.y;
    const int t = threadIdx.x;
    const int w = t >> 5;
    const int l = t & 31;

    const int b   = block_groups[n];
    const int blk = block_list[n];

    // inline KV-append detection: does any sequence append into cache block `blk`?
    int app_src = -1, app_off = 0;
#pragma unroll 8
    for (int b2 = 0; b2 < PB; b2++) {
        if (block_indices[b2] == blk) { app_src = b2; app_off = block_offsets[b2]; }
    }

    // ---- stage scaled q into smem ----
#pragma unroll
    for (int idx = t; idx < PG * PD; idx += 128)
        s_q[idx] = PSCALE * query[((size_t)b * PH + kvh * PG) * PD + idx];
    s_bias[t] = block_bias[(size_t)n * PBS + t];

    // ---- stage K block into smem: warp w loads rows w, w+4, ... (coalesced 512B rows)
    const float* kcache_base = key_cache + ((size_t)blk * PBS * PKVH + kvh) * PD;
#pragma unroll 8
    for (int r = w; r < PBS; r += 4) {
        float4 k4 = *(const float4*)(kcache_base + (size_t)r * (PKVH * PD) + 4 * l);
        *(float4*)(s_k + r * KPAD + 4 * l) = k4;
    }
    __syncthreads();

    // override appended K row (one new token) directly in smem
    if (app_src >= 0)
        s_k[app_off * KPAD + t] = k_new[((size_t)app_src * PKVH + kvh) * PD + t];
    __syncthreads();

    // ---- QK^T: thread t owns slot t; dot over D=128 from smem, 4 heads at once
    {
        float sc0 = 0.f, sc1 = 0.f, sc2 = 0.f, sc3 = 0.f;
        const float* krow = s_k + t * KPAD;
#pragma unroll
        for (int i = 0; i < 32; i++) {
            float4 k4 = *(const float4*)(krow + 4 * i);
            float4 q0 = *(const float4*)(s_q + 0 * PD + 4 * i);
            float4 q1 = *(const float4*)(s_q + 1 * PD + 4 * i);
            float4 q2 = *(const float4*)(s_q + 2 * PD + 4 * i);
            float4 q3 = *(const float4*)(s_q + 3 * PD + 4 * i);
            sc0 += q0.x*k4.x + q0.y*k4.y + q0.z*k4.z + q0.w*k4.w;
            sc1 += q1.x*k4.x + q1.y*k4.y + q1.z*k4.z + q1.w*k4.w;
            sc2 += q2.x*k4.x + q2.y*k4.y + q2.z*k4.z + q2.w*k4.w;
            sc3 += q3.x*k4.x + q3.y*k4.y + q3.z*k4.z + q3.w*k4.w;
        }
        float bia = s_bias[t];
        s_scores[0 * PBS + t] = sc0 + bia;
        s_scores[1 * PBS + t] = sc1 + bia;
        s_scores[2 * PBS + t] = sc2 + bia;
        s_scores[3 * PBS + t] = sc3 + bia;
    }
    __syncthreads();

    // ---- per-block softmax: warp w handles head g=w
    {
        const int g = w;
        float x0 = s_scores[g * PBS + l];
        float x1 = s_scores[g * PBS + l + 32];
        float x2 = s_scores[g * PBS + l + 64];
        float x3 = s_scores[g * PBS + l + 96];
        float m = fmaxf(fmaxf(x0, x1), fmaxf(x2, x3));
#pragma unroll
        for (int off = 16; off > 0; off >>= 1)
            m = fmaxf(m, __shfl_xor_sync(0xffffffffu, m, off));
        float e0 = __expf(x0 - m), e1 = __expf(x1 - m);
        float e2 = __expf(x2 - m), e3 = __expf(x3 - m);
        float sum = e0 + e1 + e2 + e3;
#pragma unroll
        for (int off = 16; off > 0; off >>= 1)
            sum += __shfl_xor_sync(0xffffffffu, sum, off);
        s_scores[g * PBS + l]      = e0;
        s_scores[g * PBS + l + 32] = e1;
        s_scores[g * PBS + l + 64] = e2;
        s_scores[g * PBS + l + 96] = e3;
        if (l == 0) {
            size_t idx = ((size_t)n * PKVH + kvh) * PG + g;
            g_m[idx] = m;
            g_l[idx] = sum;
        }
    }
    __syncthreads();

    // ---- P*V: warp w streams slots 32w..32w+31 from global (coalesced 512B rows)
    float4 o0 = make_float4(0,0,0,0), o1 = o0, o2 = o0, o3 = o0;
    const float* vcache_base = value_cache + ((size_t)blk * PBS * PKVH + kvh) * PD;
    const float* vnew_row = (app_src >= 0)
        ? (v_new + ((size_t)app_src * PKVH + kvh) * PD) : (const float*)0;
#pragma unroll 4
    for (int i = 0; i < 32; i++) {
        int s = w * 32 + i;
        float4 v4;
        if (vnew_row && s == app_off) v4 = *(const float4*)(vnew_row + 4 * l);
        else v4 = *(const float4*)(vcache_base + (size_t)s * (PKVH * PD) + 4 * l);
        float p0 = s_scores[0 * PBS + s];
        float p1 = s_scores[1 * PBS + s];
        float p2 = s_scores[2 * PBS + s];
        float p3 = s_scores[3 * PBS + s];
        o0.x += p0*v4.x; o0.y += p0*v4.y; o0.z += p0*v4.z; o0.w += p0*v4.w;
        o1.x += p1*v4.x; o1.y += p1*v4.y; o1.z += p1*v4.z; o1.w += p1*v4.w;
        o2.x += p2*v4.x; o2.y += p2*v4.y; o2.z += p2*v4.z; o2.w += p2*v4.w;
        o3.x += p3*v4.x; o3.y += p3*v4.y; o3.z += p3*v4.z; o3.w += p3*v4.w;
    }
    *(float4*)(s_po + ((w * PG + 0) * PD) + 4 * l) = o0;
    *(float4*)(s_po + ((w * PG + 1) * PD) + 4 * l) = o1;
    *(float4*)(s_po + ((w * PG + 2) * PD) + 4 * l) = o2;
    *(float4*)(s_po + ((w * PG + 3) * PD) + 4 * l) = o3;
    __syncthreads();

    // cross-warp reduce + write unnormalized partials
    {
        size_t base = (((size_t)n * PKVH + kvh) * PG) * PD;
#pragma unroll
        for (int g = 0; g < PG; g++) {
            float r = s_po[(0 * PG + g) * PD + t] + s_po[(1 * PG + g) * PD + t]
                    + s_po[(2 * PG + g) * PD + t] + s_po[(3 * PG + g) * PD + t];
            g_out[base + (size_t)g * PD + t] = r;
        }
    }
}

// ---------------- cross-block combine per (b, kvh) ----------------
__global__ __launch_bounds__(128) void combine_kernel(
    const int* __restrict__ block_groups,
    float* __restrict__ out)
{
    const int b   = blockIdx.x;
    const int kvh = blockIdx.y;
    const int t = threadIdx.x;
    const int w = t >> 5;
    const int l = t & 31;

    __shared__ int   s_bg[PNB];
    __shared__ float s_M[PG], s_invL[PG];

    for (int i = t; i < PNB; i += 128) s_bg[i] = block_groups[i];
    __syncthreads();

    {
        const int g = w;
        float M = -FLT_MAX;
        for (int n = l; n < PNB; n += 32)
            if (s_bg[n] == b)
                M = fmaxf(M, g_m[((size_t)n * PKVH + kvh) * PG + g]);
#pragma unroll
        for (int off = 16; off > 0; off >>= 1)
            M = fmaxf(M, __shfl_xor_sync(0xffffffffu, M, off));
        float L = 0.f;
        for (int n = l; n < PNB; n += 32)
            if (s_bg[n] == b) {
                size_t idx = ((size_t)n * PKVH + kvh) * PG + g;
                L += g_l[idx] * __expf(g_m[idx] - M);
            }
#pragma unroll
        for (int off = 16; off > 0; off >>= 1)
            L += __shfl_xor_sync(0xffffffffu, L, off);
        if (l == 0) {
            s_M[g] = M;
            s_invL[g] = 1.0f / fmaxf(L, 1.17549435e-38f);
        }
    }
    __syncthreads();

    float acc[PG] = {0.f, 0.f, 0.f, 0.f};
    for (int n = 0; n < PNB; n++) {
        if (s_bg[n] != b) continue;
        size_t sbase = ((size_t)n * PKVH + kvh) * PG;
#pragma unroll
        for (int g = 0; g < PG; g++) {
            float c = __expf(g_m[sbase + g] - s_M[g]) * s_invL[g];
            acc[g] += c * g_out[(sbase + g) * PD + t];
        }
    }

    size_t obase = ((size_t)b * PH + kvh * PG) * PD + t;
#pragma unroll
    for (int g = 0; g < PG; g++)
        out[obase + (size_t)g * PD] = acc[g];
}

extern "C" void kernel_launch(void* const* d_in, const int* in_sizes, int n_in,
                              void* d_out, int out_size)
{
    const float* query        = (const float*)d_in[0];
    const float* k_new        = (const float*)d_in[1];
    const float* v_new        = (const float*)d_in[2];
    const float* key_cache    = (const float*)d_in[3];
    const float* value_cache  = (const float*)d_in[4];
    const int*   block_list   = (const int*)d_in[5];
    const int*   block_groups = (const int*)d_in[6];
    const float* block_bias   = (const float*)d_in[8];
    const int*   block_indices= (const int*)d_in[9];
    const int*   block_offsets= (const int*)d_in[10];
    float* out = (float*)d_out;

    cudaFuncSetAttribute(attn_block_kernel,
                         cudaFuncAttributeMaxDynamicSharedMemorySize, SM_BYTES);

    dim3 g1(PNB, PKVH);
    attn_block_kernel<<<g1, 128, SM_BYTES>>>(query, key_cache, value_cache,
                                             k_new, v_new,
                                             block_list, block_groups, block_bias,
                                             block_indices, block_offsets);

    dim3 g2(PB, PKVH);
    combine_kernel<<<g2, 128>>>(block_groups, out);
}

// round 6
// speedup vs baseline: 2.7478x; 2.7478x over previous
#include <cuda_runtime.h>
#include <cuda_bf16.h>
#include <math.h>
#include <float.h>

#define PB   64
#define PH   32
#define PKVH 8
#define PD   128
#define PBS  128
#define PBLK_PER_SEQ 16
#define PNB  (PB * PBLK_PER_SEQ)   // 1024
#define PG   (PH / PKVH)           // 4
#define PSCALE 0.08838834764831845f
#define PNTB_CAP 2048              // >= NTB (1280)

// ---------------- scratch (allocation-free) ----------------
__device__ float g_m  [PNB * PKVH * PG];
__device__ float g_l  [PNB * PKVH * PG];
__device__ float g_out[(size_t)PNB * PKVH * PG * PD];  // 16 MB, L2-resident for combine
__device__ int   g_app[PNTB_CAP];                      // cache-block -> (src<<16)|off, or -1

// ---------------- kernel 0: build append map (replaces cache scatter) ----------------
__global__ void build_app_map_kernel(const int* __restrict__ block_indices,
                                     const int* __restrict__ block_offsets)
{
    int t = threadIdx.x;
    for (int i = t; i < PNTB_CAP; i += 256) g_app[i] = -1;
    __syncthreads();
    if (t < PB) g_app[block_indices[t]] = (t << 16) | block_offsets[t];
}

// ---------------- kernel 1: per-(block, kvh) partial attention ----------------
// 128 threads: lane l owns float4 d-slice [4l,4l+4), warp w owns slots [32w,32w+32).
__global__ __launch_bounds__(128) void attn_block_kernel(
    const float* __restrict__ query,
    const float* __restrict__ key_cache,
    const float* __restrict__ value_cache,
    const float* __restrict__ k_new,
    const float* __restrict__ v_new,
    const int*   __restrict__ block_list,
    const int*   __restrict__ block_groups,
    const float* __restrict__ block_bias)
{
    const int n   = blockIdx.x;
    const int kvh = blockIdx.y;
    const int t = threadIdx.x;
    const int w = t >> 5;
    const int l = t & 31;

    __shared__ float s_scores[PG][PBS];
    __shared__ float s_bias[PBS];
    __shared__ float s_po[4][PG][PD];

    const int b   = block_groups[n];
    const int blk = block_list[n];
    const int app = g_app[blk];
    const int app_src = (app >= 0) ? (app >> 16) : 0;
    const int app_off = (app >= 0) ? (app & 0xffff) : -1;

    s_bias[t] = block_bias[(size_t)n * PBS + t];

    // scaled q fragment per head
    float4 q4[PG];
    const float* qbase = query + (((size_t)b * PH + kvh * PG) * PD) + 4 * l;
#pragma unroll
    for (int g = 0; g < PG; g++) {
        float4 v = *(const float4*)(qbase + (size_t)g * PD);
        q4[g] = make_float4(v.x * PSCALE, v.y * PSCALE, v.z * PSCALE, v.w * PSCALE);
    }

    const size_t slot_stride = (size_t)PKVH * PD;
    const float* kbase = key_cache   + ((size_t)blk * PBS * PKVH + kvh) * PD + 4 * l;
    const float* vbase = value_cache + ((size_t)blk * PBS * PKVH + kvh) * PD + 4 * l;
    const float* knew_row = k_new + ((size_t)app_src * PKVH + kvh) * PD + 4 * l;
    const float* vnew_row = v_new + ((size_t)app_src * PKVH + kvh) * PD + 4 * l;

    // ---- QK^T (streaming loads; inline K-append override) ----
#pragma unroll 8
    for (int i = 0; i < 32; i++) {
        int s = w * 32 + i;
        const float4* kp = (s == app_off) ? (const float4*)knew_row
                                          : (const float4*)(kbase + (size_t)s * slot_stride);
        float4 k4 = __ldcs(kp);
        float p0 = q4[0].x*k4.x + q4[0].y*k4.y + q4[0].z*k4.z + q4[0].w*k4.w;
        float p1 = q4[1].x*k4.x + q4[1].y*k4.y + q4[1].z*k4.z + q4[1].w*k4.w;
        float p2 = q4[2].x*k4.x + q4[2].y*k4.y + q4[2].z*k4.z + q4[2].w*k4.w;
        float p3 = q4[3].x*k4.x + q4[3].y*k4.y + q4[3].z*k4.z + q4[3].w*k4.w;
#pragma unroll
        for (int off = 16; off > 0; off >>= 1) {
            p0 += __shfl_xor_sync(0xffffffffu, p0, off);
            p1 += __shfl_xor_sync(0xffffffffu, p1, off);
            p2 += __shfl_xor_sync(0xffffffffu, p2, off);
            p3 += __shfl_xor_sync(0xffffffffu, p3, off);
        }
        if (l == 0) {
            s_scores[0][s] = p0;
            s_scores[1][s] = p1;
            s_scores[2][s] = p2;
            s_scores[3][s] = p3;
        }
    }
    __syncthreads();

    // ---- per-block softmax: warp w handles head g=w ----
    {
        const int g = w;
        float x0 = s_scores[g][l     ] + s_bias[l     ];
        float x1 = s_scores[g][l + 32] + s_bias[l + 32];
        float x2 = s_scores[g][l + 64] + s_bias[l + 64];
        float x3 = s_scores[g][l + 96] + s_bias[l + 96];
        float m = fmaxf(fmaxf(x0, x1), fmaxf(x2, x3));
#pragma unroll
        for (int off = 16; off > 0; off >>= 1)
            m = fmaxf(m, __shfl_xor_sync(0xffffffffu, m, off));
        float e0 = __expf(x0 - m), e1 = __expf(x1 - m);
        float e2 = __expf(x2 - m), e3 = __expf(x3 - m);
        float sum = e0 + e1 + e2 + e3;
#pragma unroll
        for (int off = 16; off > 0; off >>= 1)
            sum += __shfl_xor_sync(0xffffffffu, sum, off);
        s_scores[g][l     ] = e0;
        s_scores[g][l + 32] = e1;
        s_scores[g][l + 64] = e2;
        s_scores[g][l + 96] = e3;
        if (l == 0) {
            size_t idx = ((size_t)n * PKVH + kvh) * PG + g;
            g_m[idx] = m;
            g_l[idx] = sum;
        }
    }
    __syncthreads();

    // ---- P*V (streaming loads; inline V-append override) ----
    float4 o0 = make_float4(0,0,0,0), o1 = o0, o2 = o0, o3 = o0;
#pragma unroll 8
    for (int i = 0; i < 32; i++) {
        int s = w * 32 + i;
        const float4* vp = (s == app_off) ? (const float4*)vnew_row
                                          : (const float4*)(vbase + (size_t)s * slot_stride);
        float4 v4 = __ldcs(vp);
        float p0 = s_scores[0][s];
        float p1 = s_scores[1][s];
        float p2 = s_scores[2][s];
        float p3 = s_scores[3][s];
        o0.x += p0*v4.x; o0.y += p0*v4.y; o0.z += p0*v4.z; o0.w += p0*v4.w;
        o1.x += p1*v4.x; o1.y += p1*v4.y; o1.z += p1*v4.z; o1.w += p1*v4.w;
        o2.x += p2*v4.x; o2.y += p2*v4.y; o2.z += p2*v4.z; o2.w += p2*v4.w;
        o3.x += p3*v4.x; o3.y += p3*v4.y; o3.z += p3*v4.z; o3.w += p3*v4.w;
    }
    *(float4*)(&s_po[w][0][4 * l]) = o0;
    *(float4*)(&s_po[w][1][4 * l]) = o1;
    *(float4*)(&s_po[w][2][4 * l]) = o2;
    *(float4*)(&s_po[w][3][4 * l]) = o3;
    __syncthreads();

    // cross-warp reduce + write unnormalized partial out
    {
        size_t base = (((size_t)n * PKVH + kvh) * PG) * PD;
#pragma unroll
        for (int g = 0; g < PG; g++) {
            float r = s_po[0][g][t] + s_po[1][g][t] + s_po[2][g][t] + s_po[3][g][t];
            g_out[base + (size_t)g * PD + t] = r;
        }
    }
}

// ---------------- kernel 2: cross-block combine per (b, kvh) ----------------
__global__ __launch_bounds__(128) void combine_kernel(
    const int* __restrict__ block_groups,
    float* __restrict__ out)
{
    const int b   = blockIdx.x;
    const int kvh = blockIdx.y;
    const int t = threadIdx.x;
    const int w = t >> 5;
    const int l = t & 31;

    __shared__ int   s_bg[PNB];
    __shared__ int   s_list[PNB];
    __shared__ float s_coef[PG][PNB];
    __shared__ int   s_wcnt[4], s_woff[4], s_cnt;

    for (int i = t; i < PNB; i += 128) s_bg[i] = block_groups[i];
    __syncthreads();

    // deterministic compaction: warp w owns n in [w*256, w*256+256)
    {
        int cnt = 0;
#pragma unroll
        for (int c = 0; c < 8; c++) {
            int n = w * 256 + c * 32 + l;
            unsigned bal = __ballot_sync(0xffffffffu, s_bg[n] == b);
            cnt += __popc(bal);
        }
        if (l == 0) s_wcnt[w] = cnt;
    }
    __syncthreads();
    if (t == 0) {
        int off = 0;
#pragma unroll
        for (int i = 0; i < 4; i++) { s_woff[i] = off; off += s_wcnt[i]; }
        s_cnt = off;
    }
    __syncthreads();
    {
        int off = s_woff[w];
#pragma unroll
        for (int c = 0; c < 8; c++) {
            int n = w * 256 + c * 32 + l;
            bool match = (s_bg[n] == b);
            unsigned bal = __ballot_sync(0xffffffffu, match);
            if (match) s_list[off + __popc(bal & ((1u << l) - 1u))] = n;
            off += __popc(bal);
        }
    }
    __syncthreads();
    const int cnt = s_cnt;

    // warp w computes M, L, coefficients for head g=w over the list
    {
        const int g = w;
        float M = -FLT_MAX;
        for (int i = l; i < cnt; i += 32)
            M = fmaxf(M, g_m[((size_t)s_list[i] * PKVH + kvh) * PG + g]);
#pragma unroll
        for (int off = 16; off > 0; off >>= 1)
            M = fmaxf(M, __shfl_xor_sync(0xffffffffu, M, off));
        float L = 0.f;
        for (int i = l; i < cnt; i += 32) {
            size_t idx = ((size_t)s_list[i] * PKVH + kvh) * PG + g;
            L += g_l[idx] * __expf(g_m[idx] - M);
        }
#pragma unroll
        for (int off = 16; off > 0; off >>= 1)
            L += __shfl_xor_sync(0xffffffffu, L, off);
        float invL = 1.0f / fmaxf(L, 1.17549435e-38f);
        for (int i = l; i < cnt; i += 32) {
            size_t idx = ((size_t)s_list[i] * PKVH + kvh) * PG + g;
            s_coef[g][i] = __expf(g_m[idx] - M) * invL;
        }
    }
    __syncthreads();

    float acc0 = 0.f, acc1 = 0.f, acc2 = 0.f, acc3 = 0.f;
#pragma unroll 4
    for (int i = 0; i < cnt; i++) {
        size_t base = (((size_t)s_list[i] * PKVH + kvh) * PG) * PD + t;
        acc0 += s_coef[0][i] * g_out[base];
        acc1 += s_coef[1][i] * g_out[base + PD];
        acc2 += s_coef[2][i] * g_out[base + 2 * PD];
        acc3 += s_coef[3][i] * g_out[base + 3 * PD];
    }

    size_t obase = ((size_t)b * PH + kvh * PG) * PD + t;
    out[obase]          = acc0;
    out[obase + PD]     = acc1;
    out[obase + 2 * PD] = acc2;
    out[obase + 3 * PD] = acc3;
}

// ---------------- launch ----------------
extern "C" void kernel_launch(void* const* d_in, const int* in_sizes, int n_in,
                              void* d_out, int out_size)
{
    const float* query        = (const float*)d_in[0];
    const float* k_new        = (const float*)d_in[1];
    const float* v_new        = (const float*)d_in[2];
    const float* key_cache    = (const float*)d_in[3];
    const float* value_cache  = (const float*)d_in[4];
    const int*   block_list   = (const int*)d_in[5];
    const int*   block_groups = (const int*)d_in[6];
    const float* block_bias   = (const float*)d_in[8];
    const int*   block_indices= (const int*)d_in[9];
    const int*   block_offsets= (const int*)d_in[10];
    float* out = (float*)d_out;

    build_app_map_kernel<<<1, 256>>>(block_indices, block_offsets);

    dim3 g1(PNB, PKVH);
    attn_block_kernel<<<g1, 128>>>(query, key_cache, value_cache,
                                   k_new, v_new,
                                   block_list, block_groups, block_bias);

    dim3 g2(PB, PKVH);
    combine_kernel<<<g2, 128>>>(block_groups, out);
}

// round 7
// speedup vs baseline: 2.8192x; 1.0260x over previous
#include <cuda_runtime.h>
#include <cuda_bf16.h>
#include <math.h>
#include <float.h>

#define PB   64
#define PH   32
#define PKVH 8
#define PD   128
#define PBS  128
#define PBLK_PER_SEQ 16
#define PNB  (PB * PBLK_PER_SEQ)   // 1024
#define PG   (PH / PKVH)           // 4
#define PSCALE 0.08838834764831845f
#define FULLM 0xffffffffu

// ---------------- scratch (allocation-free) ----------------
__device__ float g_m  [PNB * PKVH * PG];
__device__ float g_l  [PNB * PKVH * PG];
__device__ float g_out[(size_t)PNB * PKVH * PG * PD];  // 16 MB

// ---------------- kernel 1: per-(block, kvh) partial attention ----------------
// grid (PKVH, PNB): consecutive CTAs read adjacent kvh slices of one cache block.
// 128 threads. QK: quad of lanes owns one K row (2-stage reduce). PV: lane owns d-slice.
__global__ __launch_bounds__(128) void attn_block_kernel(
    const float* __restrict__ query,
    const float* __restrict__ key_cache,
    const float* __restrict__ value_cache,
    const float* __restrict__ k_new,
    const float* __restrict__ v_new,
    const int*   __restrict__ block_list,
    const int*   __restrict__ block_groups,
    const float* __restrict__ block_bias,
    const int*   __restrict__ block_indices,
    const int*   __restrict__ block_offsets)
{
    const int kvh = blockIdx.x;
    const int n   = blockIdx.y;
    const int t = threadIdx.x;
    const int w = t >> 5;
    const int l = t & 31;
    const int c = l & 3;          // column-group within quad

    __shared__ float s_q[PG * PD];        // scaled query (4 heads)
    __shared__ float s_scores[PG][PBS];
    __shared__ float s_bias[PBS];
    __shared__ float s_po[4][PG][PD];

    const int b   = block_groups[n];
    const int blk = block_list[n];

    // ---- inline append detection (per-warp, redundant, no sync) ----
    int app_src = 0, app_off = -1;
    {
        int bi_a = block_indices[l], bi_b = block_indices[l + 32];
        int bo_a = block_offsets[l], bo_b = block_offsets[l + 32];
        unsigned ma = __ballot_sync(FULLM, bi_a == blk);
        unsigned mb = __ballot_sync(FULLM, bi_b == blk);
        if (ma) {
            int s = __ffs(ma) - 1;
            app_src = s;
            app_off = __shfl_sync(FULLM, bo_a, s);
        } else if (mb) {
            int s = __ffs(mb) - 1;
            app_src = s + 32;
            app_off = __shfl_sync(FULLM, bo_b, s);
        }
    }

    s_bias[t] = block_bias[(size_t)n * PBS + t];
#pragma unroll
    for (int idx = t; idx < PG * PD; idx += 128)
        s_q[idx] = PSCALE * query[((size_t)b * PH + kvh * PG) * PD + idx];
    __syncthreads();

    const size_t slot_stride = (size_t)PKVH * PD;
    const float* kbase = key_cache   + ((size_t)blk * PBS * PKVH + kvh) * PD;
    const float* vbase = value_cache + ((size_t)blk * PBS * PKVH + kvh) * PD;
    const float* knew_row = k_new + ((size_t)app_src * PKVH + kvh) * PD;
    const float* vnew_row = v_new + ((size_t)app_src * PKVH + kvh) * PD;

    // ---- QK^T: quad (4 lanes) per row; warp covers 8 rows/iter, 4 iters = 32 rows
#pragma unroll
    for (int r = 0; r < 4; r++) {
        const int s = w * 32 + r * 8 + (l >> 2);
        const float* krow = (s == app_off) ? knew_row : (kbase + (size_t)s * slot_stride);
        float a0 = 0.f, a1 = 0.f, a2 = 0.f, a3 = 0.f;
#pragma unroll
        for (int j = 0; j < 8; j++) {
            const int o = 16 * j + 4 * c;
            float4 k4 = __ldcs((const float4*)(krow + o));
            float4 q0 = *(const float4*)(s_q + 0 * PD + o);
            float4 q1 = *(const float4*)(s_q + 1 * PD + o);
            float4 q2 = *(const float4*)(s_q + 2 * PD + o);
            float4 q3 = *(const float4*)(s_q + 3 * PD + o);
            a0 += q0.x*k4.x + q0.y*k4.y + q0.z*k4.z + q0.w*k4.w;
            a1 += q1.x*k4.x + q1.y*k4.y + q1.z*k4.z + q1.w*k4.w;
            a2 += q2.x*k4.x + q2.y*k4.y + q2.z*k4.z + q2.w*k4.w;
            a3 += q3.x*k4.x + q3.y*k4.y + q3.z*k4.z + q3.w*k4.w;
        }
        // reduce within quad (2 stages)
#pragma unroll
        for (int off = 1; off <= 2; off <<= 1) {
            a0 += __shfl_xor_sync(FULLM, a0, off);
            a1 += __shfl_xor_sync(FULLM, a1, off);
            a2 += __shfl_xor_sync(FULLM, a2, off);
            a3 += __shfl_xor_sync(FULLM, a3, off);
        }
        // lane c stores head c for its row
        float val = (c == 0) ? a0 : (c == 1) ? a1 : (c == 2) ? a2 : a3;
        s_scores[c][s] = val;
    }
    __syncthreads();

    // ---- per-block softmax: warp w handles head g=w ----
    {
        const int g = w;
        float x0 = s_scores[g][l     ] + s_bias[l     ];
        float x1 = s_scores[g][l + 32] + s_bias[l + 32];
        float x2 = s_scores[g][l + 64] + s_bias[l + 64];
        float x3 = s_scores[g][l + 96] + s_bias[l + 96];
        float m = fmaxf(fmaxf(x0, x1), fmaxf(x2, x3));
#pragma unroll
        for (int off = 16; off > 0; off >>= 1)
            m = fmaxf(m, __shfl_xor_sync(FULLM, m, off));
        float e0 = __expf(x0 - m), e1 = __expf(x1 - m);
        float e2 = __expf(x2 - m), e3 = __expf(x3 - m);
        float sum = e0 + e1 + e2 + e3;
#pragma unroll
        for (int off = 16; off > 0; off >>= 1)
            sum += __shfl_xor_sync(FULLM, sum, off);
        s_scores[g][l     ] = e0;
        s_scores[g][l + 32] = e1;
        s_scores[g][l + 64] = e2;
        s_scores[g][l + 96] = e3;
        if (l == 0) {
            size_t idx = ((size_t)n * PKVH + kvh) * PG + g;
            g_m[idx] = m;
            g_l[idx] = sum;
        }
    }
    __syncthreads();

    // ---- P*V: lane owns float4 d-slice [4l,4l+4), warp streams its 32 slots ----
    float4 o0 = make_float4(0,0,0,0), o1 = o0, o2 = o0, o3 = o0;
#pragma unroll 8
    for (int i = 0; i < 32; i++) {
        int s = w * 32 + i;
        const float* vrow = (s == app_off) ? vnew_row : (vbase + (size_t)s * slot_stride);
        float4 v4 = __ldcs((const float4*)(vrow + 4 * l));
        float p0 = s_scores[0][s];
        float p1 = s_scores[1][s];
        float p2 = s_scores[2][s];
        float p3 = s_scores[3][s];
        o0.x += p0*v4.x; o0.y += p0*v4.y; o0.z += p0*v4.z; o0.w += p0*v4.w;
        o1.x += p1*v4.x; o1.y += p1*v4.y; o1.z += p1*v4.z; o1.w += p1*v4.w;
        o2.x += p2*v4.x; o2.y += p2*v4.y; o2.z += p2*v4.z; o2.w += p2*v4.w;
        o3.x += p3*v4.x; o3.y += p3*v4.y; o3.z += p3*v4.z; o3.w += p3*v4.w;
    }
    *(float4*)(&s_po[w][0][4 * l]) = o0;
    *(float4*)(&s_po[w][1][4 * l]) = o1;
    *(float4*)(&s_po[w][2][4 * l]) = o2;
    *(float4*)(&s_po[w][3][4 * l]) = o3;
    __syncthreads();

    // cross-warp reduce + write unnormalized partial out
    {
        size_t base = (((size_t)n * PKVH + kvh) * PG) * PD;
#pragma unroll
        for (int g = 0; g < PG; g++) {
            float r = s_po[0][g][t] + s_po[1][g][t] + s_po[2][g][t] + s_po[3][g][t];
            g_out[base + (size_t)g * PD + t] = r;
        }
    }
}

// ---------------- kernel 2: cross-block combine per (b, kvh) ----------------
__global__ __launch_bounds__(128) void combine_kernel(
    const int* __restrict__ block_groups,
    float* __restrict__ out)
{
    const int b   = blockIdx.x;
    const int kvh = blockIdx.y;
    const int t = threadIdx.x;
    const int w = t >> 5;
    const int l = t & 31;

    __shared__ int   s_bg[PNB];
    __shared__ int   s_list[PNB];
    __shared__ float s_coef[PG][PNB];
    __shared__ int   s_wcnt[4], s_woff[4], s_cnt;

    for (int i = t; i < PNB; i += 128) s_bg[i] = block_groups[i];
    __syncthreads();

    // deterministic compaction: warp w owns n in [w*256, w*256+256)
    {
        int cnt = 0;
#pragma unroll
        for (int cch = 0; cch < 8; cch++) {
            int n = w * 256 + cch * 32 + l;
            unsigned bal = __ballot_sync(FULLM, s_bg[n] == b);
            cnt += __popc(bal);
        }
        if (l == 0) s_wcnt[w] = cnt;
    }
    __syncthreads();
    if (t == 0) {
        int off = 0;
#pragma unroll
        for (int i = 0; i < 4; i++) { s_woff[i] = off; off += s_wcnt[i]; }
        s_cnt = off;
    }
    __syncthreads();
    {
        int off = s_woff[w];
#pragma unroll
        for (int cch = 0; cch < 8; cch++) {
            int n = w * 256 + cch * 32 + l;
            bool match = (s_bg[n] == b);
            unsigned bal = __ballot_sync(FULLM, match);
            if (match) s_list[off + __popc(bal & ((1u << l) - 1u))] = n;
            off += __popc(bal);
        }
    }
    __syncthreads();
    const int cnt = s_cnt;

    // warp w computes M, L, coefficients for head g=w over the list
    {
        const int g = w;
        float M = -FLT_MAX;
        for (int i = l; i < cnt; i += 32)
            M = fmaxf(M, g_m[((size_t)s_list[i] * PKVH + kvh) * PG + g]);
#pragma unroll
        for (int off = 16; off > 0; off >>= 1)
            M = fmaxf(M, __shfl_xor_sync(FULLM, M, off));
        float L = 0.f;
        for (int i = l; i < cnt; i += 32) {
            size_t idx = ((size_t)s_list[i] * PKVH + kvh) * PG + g;
            L += g_l[idx] * __expf(g_m[idx] - M);
        }
#pragma unroll
        for (int off = 16; off > 0; off >>= 1)
            L += __shfl_xor_sync(FULLM, L, off);
        float invL = 1.0f / fmaxf(L, 1.17549435e-38f);
        for (int i = l; i < cnt; i += 32) {
            size_t idx = ((size_t)s_list[i] * PKVH + kvh) * PG + g;
            s_coef[g][i] = __expf(g_m[idx] - M) * invL;
        }
    }
    __syncthreads();

    float acc0 = 0.f, acc1 = 0.f, acc2 = 0.f, acc3 = 0.f;
#pragma unroll 4
    for (int i = 0; i < cnt; i++) {
        size_t base = (((size_t)s_list[i] * PKVH + kvh) * PG) * PD + t;
        acc0 += s_coef[0][i] * g_out[base];
        acc1 += s_coef[1][i] * g_out[base + PD];
        acc2 += s_coef[2][i] * g_out[base + 2 * PD];
        acc3 += s_coef[3][i] * g_out[base + 3 * PD];
    }

    size_t obase = ((size_t)b * PH + kvh * PG) * PD + t;
    out[obase]          = acc0;
    out[obase + PD]     = acc1;
    out[obase + 2 * PD] = acc2;
    out[obase + 3 * PD] = acc3;
}

// ---------------- launch ----------------
extern "C" void kernel_launch(void* const* d_in, const int* in_sizes, int n_in,
                              void* d_out, int out_size)
{
    const float* query        = (const float*)d_in[0];
    const float* k_new        = (const float*)d_in[1];
    const float* v_new        = (const float*)d_in[2];
    const float* key_cache    = (const float*)d_in[3];
    const float* value_cache  = (const float*)d_in[4];
    const int*   block_list   = (const int*)d_in[5];
    const int*   block_groups = (const int*)d_in[6];
    const float* block_bias   = (const float*)d_in[8];
    const int*   block_indices= (const int*)d_in[9];
    const int*   block_offsets= (const int*)d_in[10];
    float* out = (float*)d_out;

    dim3 g1(PKVH, PNB);
    attn_block_kernel<<<g1, 128>>>(query, key_cache, value_cache,
                                   k_new, v_new,
                                   block_list, block_groups, block_bias,
                                   block_indices, block_offsets);

    dim3 g2(PB, PKVH);
    combine_kernel<<<g2, 128>>>(block_groups, out);
}